// round 17
// baseline (speedup 1.0000x reference)
#include <cuda_runtime.h>
#include <cuda_bf16.h>
#include <mma.h>
#include <stdint.h>
#include <cstdint>
#include <math.h>

using namespace nvcuda;

#define BATCH 2
#define SEQ 128
#define NH 4
#define DKK 128
#define DD 512
#define NBB 4

// ---------------- scratch (device globals; no allocation allowed) ----------------
__device__ float g_qkv[2][3][BATCH][NH][SEQ][DKK]; // [fam(m/c)][q/k/v][b][h][n][k]
__device__ float g_bbQ[BATCH][NH][NBB][NBB][DKK];
__device__ float g_bbK[BATCH][NH][NBB][NBB][DKK];
__device__ float g_pq[BATCH][NH][SEQ][DKK];
__device__ float g_pk[BATCH][NH][SEQ][DKK];
__device__ float g_FQ[BATCH][NH][SEQ][NBB][2*DKK]; // [m(0..127) | sqrt(c)(128..255)]
__device__ float g_FK[BATCH][NH][SEQ][NBB][2*DKK];
__device__ float g_sqnq[BATCH][NH][SEQ][NBB];
__device__ float g_sqnk[BATCH][NH][SEQ][NBB];
__device__ int   g_perm[BATCH][SEQ];
__device__ int   g_off[BATCH][NBB + 1];
__device__ float g_scs[BATCH*NH][SEQ][SEQ];
__device__ float g_ctx[2][BATCH][SEQ][DD];
__device__ float g_tmp[2][BATCH][SEQ][DD];

// bf16 hi/lo operand copies (pre-split, W pre-transposed)
__device__ __nv_bfloat16 g_Xh[4][256][512];   // [fam*2+pair][m][k]
__device__ __nv_bfloat16 g_Xl[4][256][512];
__device__ __nv_bfloat16 g_WTh[12][512][512]; // [(fam*2+pair)*3+s][hk][k]  (transposed)
__device__ __nv_bfloat16 g_WTl[12][512][512];

// =====================================================================
// K_pre: fused prep_x + prep_w + perm. grid 3586 x 256 thr.
// =====================================================================
__global__ void __launch_bounds__(256) prep_all(
    const float* __restrict__ x_m, const float* __restrict__ b_m,
    const float* __restrict__ x_c, const float* __restrict__ b_c,
    const float* __restrict__ Wxm, const float* __restrict__ Wbm,
    const float* __restrict__ Wxc, const float* __restrict__ Wbc,
    const int* __restrict__ b_seq)
{
    const int blk = blockIdx.x;
    const int t = threadIdx.x;

    if (blk < 512) {
        // ---- X convert ----
        int idx = blk * 256 + t;
        int a = idx >> 15;
        int r = idx & 32767;
        const float* src = (a == 0) ? x_m : (a == 1) ? b_m : (a == 2) ? x_c : b_c;
        float4 v = ((const float4*)src)[r];
        __nv_bfloat16* oh = &g_Xh[0][0][0] + (size_t)a * 131072 + (size_t)r * 4;
        __nv_bfloat16* ol = &g_Xl[0][0][0] + (size_t)a * 131072 + (size_t)r * 4;
        float vv[4];
        vv[0] = v.x; vv[1] = v.y; vv[2] = v.z; vv[3] = v.w;
#pragma unroll
        for (int e = 0; e < 4; ++e) {
            __nv_bfloat16 hi = __float2bfloat16(vv[e]);
            oh[e] = hi;
            ol[e] = __float2bfloat16(vv[e] - __bfloat162float(hi));
        }
    } else if (blk < 3584) {
        // ---- W transpose + convert ----
        int idx2 = blk - 512;
        int mi = idx2 >> 8;
        int rem = idx2 & 255;
        int hk0 = (rem >> 4) * 32;
        int d0  = (rem & 15) * 32;
        int fam = mi / 6;
        int pair = (mi / 3) & 1;
        int s = mi % 3;
        const float* src = (fam == 0) ? (pair == 0 ? Wxm : Wbm)
                                      : (pair == 0 ? Wxc : Wbc);
        src += (size_t)s * 262144;

        __shared__ float tile[32][33];
        int r = t >> 3, c4 = (t & 7) * 4;
        float4 v = *(const float4*)&src[(size_t)(d0 + r) * 512 + hk0 + c4];
        tile[r][c4 + 0] = v.x; tile[r][c4 + 1] = v.y;
        tile[r][c4 + 2] = v.z; tile[r][c4 + 3] = v.w;
        __syncthreads();

        __nv_bfloat16* oh = &g_WTh[0][0][0] + (size_t)mi * 262144 + (size_t)(hk0 + r) * 512 + d0 + c4;
        __nv_bfloat16* ol = &g_WTl[0][0][0] + (size_t)mi * 262144 + (size_t)(hk0 + r) * 512 + d0 + c4;
#pragma unroll
        for (int e = 0; e < 4; ++e) {
            float f = tile[c4 + e][r];
            __nv_bfloat16 hi = __float2bfloat16(f);
            oh[e] = hi;
            ol[e] = __float2bfloat16(f - __bfloat162float(hi));
        }
    } else {
        // ---- ballot counting sort (1 block per batch) ----
        int b = blk - 3584;
        __shared__ int wcnt[4][4];
        int w = t >> 5, lane = t & 31;
        int key = 0, rank_w = 0;
        if (t < 128) {
            key = b_seq[b * 128 + t];
            unsigned b0 = __ballot_sync(0xFFFFFFFFu, key == 0);
            unsigned b1 = __ballot_sync(0xFFFFFFFFu, key == 1);
            unsigned b2 = __ballot_sync(0xFFFFFFFFu, key == 2);
            unsigned b3 = __ballot_sync(0xFFFFFFFFu, key == 3);
            if (lane == 0) {
                wcnt[w][0] = __popc(b0); wcnt[w][1] = __popc(b1);
                wcnt[w][2] = __popc(b2); wcnt[w][3] = __popc(b3);
            }
            unsigned mymask = (key == 0) ? b0 : (key == 1) ? b1 : (key == 2) ? b2 : b3;
            rank_w = __popc(mymask & ((1u << lane) - 1u));
        }
        __syncthreads();
        if (t < 128) {
            int cnt[4];
#pragma unroll
            for (int k = 0; k < 4; ++k)
                cnt[k] = wcnt[0][k] + wcnt[1][k] + wcnt[2][k] + wcnt[3][k];
            int off = 0;
#pragma unroll
            for (int k = 0; k < 4; ++k) if (k < key) off += cnt[k];
            int pre = 0;
#pragma unroll
            for (int w2 = 0; w2 < 4; ++w2) if (w2 < w) pre += wcnt[w2][key];
            g_perm[b][off + pre + rank_w] = t;
            if (t < 5) {
                int o = 0;
                for (int k = 0; k < t; ++k) o += cnt[k];
                g_off[b][t] = o;
            }
        }
    }
}

// =====================================================================
// K_gemm: fused proj (wmma, blocks [0,96)) + linqk (blocks [96,168)).
// =====================================================================
#define PROJ_SMEM 55296

__global__ void __launch_bounds__(256) gemm_fused(
    const float* __restrict__ p_m,  const float* __restrict__ bb_m,
    const float* __restrict__ Wq1_w, const float* __restrict__ Wq1_b,
    const float* __restrict__ Wq2_w, const float* __restrict__ Wq2_b,
    const float* __restrict__ Wk1_w, const float* __restrict__ Wk1_b,
    const float* __restrict__ Wk2_w, const float* __restrict__ Wk2_b)
{
    const int t = threadIdx.x;

    if (blockIdx.x < 96) {
        // ================= proj path =================
        extern __shared__ char ds[];
        __nv_bfloat16* Ah = (__nv_bfloat16*)ds;       // [128][72]
        __nv_bfloat16* Al = Ah + 128 * 72;
        __nv_bfloat16* Bh = Al + 128 * 72;            // [64][72]
        __nv_bfloat16* Bl = Bh + 64 * 72;

        const int u = blockIdx.x;
        const int fam = u / 48;
        const int v = u % 48;
        const int m0 = (v / 24) * 128;
        const int n0g = (v % 24) * 64;
        const int s_idx = n0g >> 9;
        const int cbase = n0g & 511;

        const int w = t >> 5;
        const int wm = (w >> 1) * 32;
        const int wn = (w & 1) * 32;

        wmma::fragment<wmma::accumulator, 16, 16, 16, float> acc[2][2];
#pragma unroll
        for (int r = 0; r < 2; ++r)
#pragma unroll
            for (int c = 0; c < 2; ++c) wmma::fill_fragment(acc[r][c], 0.f);

        uint4 pf[12];

        // prefetch chunk 0
        {
            const int ai = fam * 2;
            const int mi = ai * 3 + s_idx;
            const __nv_bfloat16* Axh = &g_Xh[ai][m0][0];
            const __nv_bfloat16* Axl = &g_Xl[ai][m0][0];
            const __nv_bfloat16* Bxh = &g_WTh[0][0][0] + (size_t)mi * 262144 + (size_t)cbase * 512;
            const __nv_bfloat16* Bxl = &g_WTl[0][0][0] + (size_t)mi * 262144 + (size_t)cbase * 512;
#pragma unroll
            for (int q = 0; q < 4; ++q) {
                int s = t + 256 * q;
                int r = s >> 3, kb = s & 7;
                pf[q]     = *(const uint4*)(Axh + (size_t)r * 512 + kb * 8);
                pf[4 + q] = *(const uint4*)(Axl + (size_t)r * 512 + kb * 8);
            }
#pragma unroll
            for (int q = 0; q < 2; ++q) {
                int s = t + 256 * q;
                int r = s >> 3, kb = s & 7;
                pf[8 + q]  = *(const uint4*)(Bxh + (size_t)r * 512 + kb * 8);
                pf[10 + q] = *(const uint4*)(Bxl + (size_t)r * 512 + kb * 8);
            }
        }

        for (int c = 0; c < 16; ++c) {
#pragma unroll
            for (int q = 0; q < 4; ++q) {
                int s = t + 256 * q;
                int r = s >> 3, kb = s & 7;
                *(uint4*)((char*)Ah + (size_t)r * 144 + kb * 16) = pf[q];
                *(uint4*)((char*)Al + (size_t)r * 144 + kb * 16) = pf[4 + q];
            }
#pragma unroll
            for (int q = 0; q < 2; ++q) {
                int s = t + 256 * q;
                int r = s >> 3, kb = s & 7;
                *(uint4*)((char*)Bh + (size_t)r * 144 + kb * 16) = pf[8 + q];
                *(uint4*)((char*)Bl + (size_t)r * 144 + kb * 16) = pf[10 + q];
            }
            __syncthreads();

            if (c + 1 < 16) {
                const int nx = c + 1;
                const int pair = nx >> 3;
                const int kk = (nx & 7) * 64;
                const int ai = fam * 2 + pair;
                const int mi = ai * 3 + s_idx;
                const __nv_bfloat16* Axh = &g_Xh[ai][m0][kk];
                const __nv_bfloat16* Axl = &g_Xl[ai][m0][kk];
                const __nv_bfloat16* Bxh = &g_WTh[0][0][0] + (size_t)mi * 262144 + (size_t)cbase * 512 + kk;
                const __nv_bfloat16* Bxl = &g_WTl[0][0][0] + (size_t)mi * 262144 + (size_t)cbase * 512 + kk;
#pragma unroll
                for (int q = 0; q < 4; ++q) {
                    int s = t + 256 * q;
                    int r = s >> 3, kb = s & 7;
                    pf[q]     = *(const uint4*)(Axh + (size_t)r * 512 + kb * 8);
                    pf[4 + q] = *(const uint4*)(Axl + (size_t)r * 512 + kb * 8);
                }
#pragma unroll
                for (int q = 0; q < 2; ++q) {
                    int s = t + 256 * q;
                    int r = s >> 3, kb = s & 7;
                    pf[8 + q]  = *(const uint4*)(Bxh + (size_t)r * 512 + kb * 8);
                    pf[10 + q] = *(const uint4*)(Bxl + (size_t)r * 512 + kb * 8);
                }
            }

#pragma unroll
            for (int ks = 0; ks < 4; ++ks) {
                wmma::fragment<wmma::matrix_a, 16, 16, 16, __nv_bfloat16, wmma::row_major> ah[2], al[2];
                wmma::fragment<wmma::matrix_b, 16, 16, 16, __nv_bfloat16, wmma::col_major> bh[2], bl[2];
#pragma unroll
                for (int r = 0; r < 2; ++r) {
                    wmma::load_matrix_sync(ah[r], Ah + (wm + 16 * r) * 72 + ks * 16, 72);
                    wmma::load_matrix_sync(al[r], Al + (wm + 16 * r) * 72 + ks * 16, 72);
                }
#pragma unroll
                for (int cb = 0; cb < 2; ++cb) {
                    wmma::load_matrix_sync(bh[cb], Bh + (wn + 16 * cb) * 72 + ks * 16, 72);
                    wmma::load_matrix_sync(bl[cb], Bl + (wn + 16 * cb) * 72 + ks * 16, 72);
                }
#pragma unroll
                for (int r = 0; r < 2; ++r)
#pragma unroll
                    for (int cb = 0; cb < 2; ++cb) {
                        wmma::mma_sync(acc[r][cb], ah[r], bh[cb], acc[r][cb]);
                        wmma::mma_sync(acc[r][cb], ah[r], bl[cb], acc[r][cb]);
                        wmma::mma_sync(acc[r][cb], al[r], bh[cb], acc[r][cb]);
                    }
            }
            __syncthreads();
        }

        const int h_idx = cbase >> 7;
        const int k0 = cbase & 127;
        const int b = m0 >> 7;
        float* outp = &g_qkv[fam][s_idx][b][h_idx][0][k0];

#pragma unroll
        for (int r = 0; r < 2; ++r)
#pragma unroll
            for (int cb = 0; cb < 2; ++cb) {
                if (fam == 1) {
#pragma unroll
                    for (int e = 0; e < acc[r][cb].num_elements; ++e) {
                        float vv = acc[r][cb].x[e];
                        acc[r][cb].x[e] = (vv > 0.f) ? (vv + 1.f) : expf(vv);
                    }
                }
                wmma::store_matrix_sync(&outp[(size_t)(wm + 16 * r) * 128 + wn + 16 * cb],
                                        acc[r][cb], 128, wmma::mem_row_major);
            }
    } else {
        // ================= linqk path =================
        const int u2 = blockIdx.x - 96;
        const int sel = u2 / 36;
        const int rr2 = u2 % 36;
        const int m0 = (rr2 >> 1) * 64;
        const int n0 = (rr2 & 1) * 64;
        const bool bbreg = (m0 >= 1024);

        const float* W    = sel ? (bbreg ? Wk1_w : Wk2_w) : (bbreg ? Wq1_w : Wq2_w);
        const float* bias = sel ? (bbreg ? Wk1_b : Wk2_b) : (bbreg ? Wq1_b : Wq2_b);

        const int tx = t & 15, ty = t >> 4;

        __shared__ __align__(16) float As[16][68];
        __shared__ __align__(16) float Bs[16][68];

        float acc[4][4] = {};

        const int a_row = t >> 2;
        const int a_k4  = (t & 3) * 4;

        for (int kk = 0; kk < 128; kk += 16) {
            {
                int r = m0 + a_row;
                const float* src;
                if (r < 1024) {
                    int b = r >> 9, h = (r >> 7) & 3, n = r & 127;
                    src = p_m + (size_t)(b * 128 + n) * 512 + h * 128 + kk + a_k4;
                } else {
                    int r2 = r - 1024;
                    int b = r2 >> 6, h = (r2 >> 4) & 3, nn = r2 & 15;
                    src = bb_m + (size_t)(b * 16 + nn) * 512 + h * 128 + kk + a_k4;
                }
                float4 av = *(const float4*)src;
                As[a_k4 + 0][a_row] = av.x;
                As[a_k4 + 1][a_row] = av.y;
                As[a_k4 + 2][a_row] = av.z;
                As[a_k4 + 3][a_row] = av.w;
            }
            {
                int c = t >> 2, k4 = (t & 3) * 4;
                float4 bv = *(const float4*)&W[(size_t)(n0 + c) * 128 + kk + k4];
                Bs[k4 + 0][c] = bv.x;
                Bs[k4 + 1][c] = bv.y;
                Bs[k4 + 2][c] = bv.z;
                Bs[k4 + 3][c] = bv.w;
            }
            __syncthreads();
#pragma unroll
            for (int kd = 0; kd < 16; ++kd) {
                float4 a4 = *(const float4*)&As[kd][ty * 4];
                float4 b4 = *(const float4*)&Bs[kd][tx * 4];
                float a[4] = {a4.x, a4.y, a4.z, a4.w};
                float bb[4] = {b4.x, b4.y, b4.z, b4.w};
#pragma unroll
                for (int r = 0; r < 4; ++r)
#pragma unroll
                    for (int c = 0; c < 4; ++c) acc[r][c] += a[r] * bb[c];
            }
            __syncthreads();
        }

        float* outp = sel ? &g_pk[0][0][0][0] : &g_pq[0][0][0][0];
        float* outb = sel ? &g_bbK[0][0][0][0][0] : &g_bbQ[0][0][0][0][0];
#pragma unroll
        for (int r = 0; r < 4; ++r) {
            int rr = m0 + ty * 4 + r;
#pragma unroll
            for (int c = 0; c < 4; ++c) {
                int col = n0 + tx * 4 + c;
                float v = acc[r][c] + bias[col];
                if (rr < 1024) outp[(size_t)rr * 128 + col] = v;
                else           outb[(size_t)(rr - 1024) * 128 + col] = v;
            }
        }
    }
}

// =====================================================================
// K3: tri-SAGP fusion -> FQ/FK + squared norms.
// =====================================================================
__global__ void __launch_bounds__(128) build_fqfk(const float* __restrict__ bb_c,
                                                  const float* __restrict__ p_c,
                                                  const int* __restrict__ b_seq)
{
    int r = blockIdx.x;                 // 0..1023 = (b,h,i)
    int b  = r >> 9;
    int hh = (r >> 7) & 3;
    int i  = r & 127;
    int t  = threadIdx.x;               // 128
    int w = t >> 5, lane = t & 31;
    const float eps = 1e-24f;

    __shared__ float rq[4][4];
    __shared__ float rk[4][4];

    int si = b_seq[b * 128 + i];
    float c3 = p_c[(size_t)(b * 128 + i) * 512 + hh * 128 + t];
    float p3 = 1.f / fmaxf(c3, eps);

    float nq[4], nk[4];

    {
        float m1 = g_qkv[0][0][b][hh][i][t];
        float c1 = g_qkv[1][0][b][hh][i][t];
        float m3 = g_pq[b][hh][i][t];
        float p1 = 1.f / fmaxf(c1, eps);
        float base_m = m1 * p1 + m3 * p3;
        float base_p = p1 + p3;
#pragma unroll
        for (int sb = 0; sb < 4; ++sb) {
            float m2 = g_bbQ[b][hh][sb][si][t];
            float c2 = bb_c[(size_t)((b * 4 + sb) * 4 + si) * 512 + hh * 128 + t];
            float p2 = 1.f / fmaxf(c2, eps);
            float cf = 1.f / (base_p + p2);
            float mf = cf * (base_m + m2 * p2);
            float cfc = fmaxf(cf, eps);
            g_FQ[b][hh][i][sb][t]       = mf;
            g_FQ[b][hh][i][sb][128 + t] = sqrtf(cfc);
            nq[sb] = mf * mf + cfc;
        }
    }
    {
        float m1 = g_qkv[0][1][b][hh][i][t];
        float c1 = g_qkv[1][1][b][hh][i][t];
        float m3 = g_pk[b][hh][i][t];
        float p1 = 1.f / fmaxf(c1, eps);
        float base_m = m1 * p1 + m3 * p3;
        float base_p = p1 + p3;
        int sj = si;
#pragma unroll
        for (int sa = 0; sa < 4; ++sa) {
            float m2 = g_bbK[b][hh][sj][sa][t];
            float c2 = bb_c[(size_t)((b * 4 + sj) * 4 + sa) * 512 + hh * 128 + t];
            float p2 = 1.f / fmaxf(c2, eps);
            float cf = 1.f / (base_p + p2);
            float mf = cf * (base_m + m2 * p2);
            float cfc = fmaxf(cf, eps);
            g_FK[b][hh][i][sa][t]       = mf;
            g_FK[b][hh][i][sa][128 + t] = sqrtf(cfc);
            nk[sa] = mf * mf + cfc;
        }
    }

#pragma unroll
    for (int sb = 0; sb < 4; ++sb) {
        float a = nq[sb];
        float c = nk[sb];
#pragma unroll
        for (int o = 16; o; o >>= 1) {
            a += __shfl_xor_sync(0xFFFFFFFFu, a, o);
            c += __shfl_xor_sync(0xFFFFFFFFu, c, o);
        }
        if (lane == 0) { rq[w][sb] = a; rk[w][sb] = c; }
    }
    __syncthreads();
    if (t < 4) {
        g_sqnq[b][hh][i][t] = rq[0][t] + rq[1][t] + rq[2][t] + rq[3][t];
    } else if (t < 8) {
        int sb = t - 4;
        g_sqnk[b][hh][i][sb] = rk[0][sb] + rk[1][sb] + rk[2][sb] + rk[3][sb];
    }
}

// =====================================================================
// K4a: bucketed score GEMM. 128 thr, K-split halves, 4x4 register tiles,
// register-prefetched (double-buffered) global loads.
// =====================================================================
__global__ void __launch_bounds__(128) scores_kernel()
{
    const int bh = blockIdx.z;
    const int b = bh >> 2, h = bh & 3;
    const int si = blockIdx.y >> 2, sb = blockIdx.y & 3;
    const int ti = (blockIdx.x >> 2) * 32, tj = (blockIdx.x & 3) * 32;

    const int rbase = g_off[b][si], rcnt = g_off[b][si + 1] - rbase;
    const int cbase = g_off[b][sb], ccnt = g_off[b][sb + 1] - cbase;
    if (ti >= rcnt || tj >= ccnt) return;

    const int t = threadIdx.x;
    const int half = t >> 6;            // K-split: half 0 -> K[0,128), half 1 -> K[128,256)
    const int lt = t & 63;
    const int tx = lt & 7;
    const int ty = lt >> 3;

    __shared__ __align__(16) float As[2][16][36];
    __shared__ __align__(16) float Bs[2][16][36];
    __shared__ __align__(16) float Ps[32][33];
    __shared__ int rid[32], cid[32];
    __shared__ float sqr[32], sqc[32];

    if (t < 32) {
        int pr = ti + t; if (pr > rcnt - 1) pr = rcnt - 1;
        int id = g_perm[b][rbase + pr];
        rid[t] = id;
        sqr[t] = g_sqnq[b][h][id][sb];
    } else if (t < 64) {
        int u = t - 32;
        int pc = tj + u; if (pc > ccnt - 1) pc = ccnt - 1;
        int id = g_perm[b][cbase + pc];
        cid[u] = id;
        sqc[u] = g_sqnk[b][h][id][si];
    }
    __syncthreads();

    const int kh = half * 128;
    const int sr0 = lt >> 2;            // rows 0..15
    const int sr1 = sr0 + 16;
    const int sk4 = (lt & 3) * 4;

    // hoist gather addresses to registers
    const float* aRow0 = &g_FQ[b][h][rid[sr0]][sb][kh + sk4];
    const float* aRow1 = &g_FQ[b][h][rid[sr1]][sb][kh + sk4];
    const float* bRow0 = &g_FK[b][h][cid[sr0]][si][kh + sk4];
    const float* bRow1 = &g_FK[b][h][cid[sr1]][si][kh + sk4];

    float acc[4][4] = {};
    float4 pa0, pa1, pb0, pb1;

    // prefetch chunk 0
    pa0 = *(const float4*)(aRow0);
    pa1 = *(const float4*)(aRow1);
    pb0 = *(const float4*)(bRow0);
    pb1 = *(const float4*)(bRow1);

    for (int it = 0; it < 8; ++it) {
        // store prefetched chunk into smem
        As[half][sk4 + 0][sr0] = pa0.x; As[half][sk4 + 1][sr0] = pa0.y;
        As[half][sk4 + 2][sr0] = pa0.z; As[half][sk4 + 3][sr0] = pa0.w;
        As[half][sk4 + 0][sr1] = pa1.x; As[half][sk4 + 1][sr1] = pa1.y;
        As[half][sk4 + 2][sr1] = pa1.z; As[half][sk4 + 3][sr1] = pa1.w;
        Bs[half][sk4 + 0][sr0] = pb0.x; Bs[half][sk4 + 1][sr0] = pb0.y;
        Bs[half][sk4 + 2][sr0] = pb0.z; Bs[half][sk4 + 3][sr0] = pb0.w;
        Bs[half][sk4 + 0][sr1] = pb1.x; Bs[half][sk4 + 1][sr1] = pb1.y;
        Bs[half][sk4 + 2][sr1] = pb1.z; Bs[half][sk4 + 3][sr1] = pb1.w;
        __syncthreads();

        // prefetch next chunk (overlaps FFMA phase)
        if (it + 1 < 8) {
            int kk = (it + 1) * 16;
            pa0 = *(const float4*)(aRow0 + kk);
            pa1 = *(const float4*)(aRow1 + kk);
            pb0 = *(const float4*)(bRow0 + kk);
            pb1 = *(const float4*)(bRow1 + kk);
        }

#pragma unroll
        for (int kd = 0; kd < 16; ++kd) {
            float4 a4 = *(const float4*)&As[half][kd][ty * 4];
            float4 b4 = *(const float4*)&Bs[half][kd][tx * 4];
            float a[4] = {a4.x, a4.y, a4.z, a4.w};
            float bb[4] = {b4.x, b4.y, b4.z, b4.w};
#pragma unroll
            for (int r = 0; r < 4; ++r)
#pragma unroll
                for (int c = 0; c < 4; ++c) acc[r][c] += a[r] * bb[c];
        }
        __syncthreads();
    }

    // combine halves
    if (half == 0) {
#pragma unroll
        for (int r = 0; r < 4; ++r)
#pragma unroll
            for (int c = 0; c < 4; ++c)
                Ps[ty * 4 + r][tx * 4 + c] = acc[r][c];
    }
    __syncthreads();
    if (half == 1) {
        const float scale = 0.08838834764831845f;   // 1/sqrt(128)
#pragma unroll
        for (int r = 0; r < 4; ++r) {
            int pr = ti + ty * 4 + r;
            if (pr >= rcnt) continue;
#pragma unroll
            for (int c = 0; c < 4; ++c) {
                int pc = tj + tx * 4 + c;
                if (pc >= ccnt) continue;
                float dot = acc[r][c] + Ps[ty * 4 + r][tx * 4 + c];
                float w2v = sqr[ty * 4 + r] + sqc[tx * 4 + c] - 2.f * dot;
                g_scs[bh][rbase + pr][cbase + pc] = -w2v * scale;
            }
        }
    }
}

// =====================================================================
// K4b: softmax + probs scatter + context.
// =====================================================================
__global__ void __launch_bounds__(256) softmax_ctx_kernel(float* __restrict__ out_probs)
{
    const int blk = blockIdx.x;
    const int bh = blk >> 4;
    const int b = bh >> 2, h = bh & 3;
    const int i0 = (blk & 15) * 8;
    const int t = threadIdx.x;
    const int lane = t & 31;

    __shared__ float sc[8 * 128];
    __shared__ int perm_s[128];
    __shared__ float ctxm[1024], ctxc[1024];

    if (t < 128) perm_s[t] = g_perm[b][t];
    {
        const float4* src = (const float4*)&g_scs[bh][i0][0];
        ((float4*)sc)[t] = src[t];
    }
    __syncthreads();

    {
        int w = t >> 5;
        float4* row = (float4*)(sc + w * 128);
        float4 x4 = row[lane];
        float m = fmaxf(fmaxf(x4.x, x4.y), fmaxf(x4.z, x4.w));
#pragma unroll
        for (int o = 16; o; o >>= 1) m = fmaxf(m, __shfl_xor_sync(0xFFFFFFFFu, m, o));
        float e0 = expf(x4.x - m), e1 = expf(x4.y - m);
        float e2 = expf(x4.z - m), e3 = expf(x4.w - m);
        float s = e0 + e1 + e2 + e3;
#pragma unroll
        for (int o = 16; o; o >>= 1) s += __shfl_xor_sync(0xFFFFFFFFu, s, o);
        float inv = 1.f / s;
        float4 p4 = make_float4(e0 * inv, e1 * inv, e2 * inv, e3 * inv);
        row[lane] = p4;
        int i = perm_s[i0 + w];
        float* op = out_probs + (size_t)(bh * 128 + i) * 128;
        op[perm_s[4 * lane + 0]] = p4.x;
        op[perm_s[4 * lane + 1]] = p4.y;
        op[perm_s[4 * lane + 2]] = p4.z;
        op[perm_s[4 * lane + 3]] = p4.w;
    }
    __syncthreads();

    {
        int k = t & 127, half = t >> 7;
        float am[8] = {}, ac[8] = {};
        const float* v1 = &g_qkv[0][2][b][h][0][0];
        const float* v2 = &g_qkv[1][2][b][h][0][0];
        int j0 = half * 64;
#pragma unroll 4
        for (int pj = j0; pj < j0 + 64; ++pj) {
            int jv = perm_s[pj];
            float x1 = v1[(size_t)jv * 128 + k];
            float x2 = v2[(size_t)jv * 128 + k];
#pragma unroll
            for (int il = 0; il < 8; ++il) {
                float p = sc[il * 128 + pj];
                am[il] += p * x1;
                ac[il] += p * p * x2;
            }
        }
        if (half == 0) {
#pragma unroll
            for (int il = 0; il < 8; ++il) {
                ctxm[il * 128 + k] = am[il];
                ctxc[il * 128 + k] = ac[il];
            }
        }
        __syncthreads();
        if (half == 1) {
#pragma unroll
            for (int il = 0; il < 8; ++il) {
                int i = perm_s[i0 + il];
                g_ctx[0][b][i][h * 128 + k] = am[il] + ctxm[il * 128 + k];
                g_ctx[1][b][i][h * 128 + k] = ac[il] + ctxc[il * 128 + k];
            }
        }
    }
}

// =====================================================================
// K5: output GEMM + bias + residual.
// =====================================================================
__global__ void __launch_bounds__(128) outgemm_kernel(
    const float* __restrict__ mean_w, const float* __restrict__ mean_b,
    const float* __restrict__ cov_w,  const float* __restrict__ cov_b,
    const float* __restrict__ x_m,    const float* __restrict__ x_c)
{
    int z = blockIdx.z;
    const float* W     = z ? cov_w  : mean_w;
    const float* bias  = z ? cov_b  : mean_b;
    const float* resid = z ? x_c    : x_m;
    const float* A = &g_ctx[z][0][0][0];
    float* out = &g_tmp[z][0][0][0];

    const int m0 = blockIdx.x * 32;
    const int n0 = blockIdx.y * 64;
    const int tid = threadIdx.x;
    const int tx = tid & 15, ty = tid >> 4;

    __shared__ __align__(16) float As[16][36];
    __shared__ __align__(16) float Bs[16][68];
    float acc[4][4] = {};

    const int a_row = tid >> 2;
    const int a_k4  = (tid & 3) * 4;

    for (int kk = 0; kk < 512; kk += 16) {
        float4 av = *(const float4*)&A[(size_t)(m0 + a_row) * 512 + kk + a_k4];
        As[a_k4 + 0][a_row] = av.x;
        As[a_k4 + 1][a_row] = av.y;
        As[a_k4 + 2][a_row] = av.z;
        As[a_k4 + 3][a_row] = av.w;
        {
            int c = tid >> 2, k4 = (tid & 3) * 4;
            float4 bv = *(const float4*)&W[(size_t)(n0 + c) * 512 + kk + k4];
            Bs[k4 + 0][c] = bv.x; Bs[k4 + 1][c] = bv.y;
            Bs[k4 + 2][c] = bv.z; Bs[k4 + 3][c] = bv.w;
            int c2 = c + 32;
            float4 bw = *(const float4*)&W[(size_t)(n0 + c2) * 512 + kk + k4];
            Bs[k4 + 0][c2] = bw.x; Bs[k4 + 1][c2] = bw.y;
            Bs[k4 + 2][c2] = bw.z; Bs[k4 + 3][c2] = bw.w;
        }
        __syncthreads();
#pragma unroll
        for (int kd = 0; kd < 16; ++kd) {
            float4 a4 = *(const float4*)&As[kd][ty * 4];
            float4 b4 = *(const float4*)&Bs[kd][tx * 4];
            float a[4] = {a4.x, a4.y, a4.z, a4.w};
            float bb[4] = {b4.x, b4.y, b4.z, b4.w};
#pragma unroll
            for (int r = 0; r < 4; ++r)
#pragma unroll
                for (int c = 0; c < 4; ++c) acc[r][c] += a[r] * bb[c];
        }
        __syncthreads();
    }

#pragma unroll
    for (int r = 0; r < 4; ++r) {
        int m = m0 + ty * 4 + r;
#pragma unroll
        for (int c = 0; c < 4; ++c) {
            int d = n0 + tx * 4 + c;
            out[(size_t)m * 512 + d] = acc[r][c] + bias[d] + resid[(size_t)m * 512 + d];
        }
    }
}

// =====================================================================
// K6: LayerNorm -> d_out
// =====================================================================
__global__ void ln_kernel(const float* __restrict__ ln_w, const float* __restrict__ ln_b,
                          float* __restrict__ d_out_f)
{
    int blk = blockIdx.x;
    int z = blk >> 8;
    int row = blk & 255;
    int tid = threadIdx.x;
    int w = tid >> 5, lane = tid & 31;
    __shared__ float red[8];

    const float* x = &g_tmp[z][0][0][0] + (size_t)row * 512;
    float a0 = x[tid], a1 = x[tid + 256];

    float s = a0 + a1;
#pragma unroll
    for (int o = 16; o; o >>= 1) s += __shfl_xor_sync(0xFFFFFFFFu, s, o);
    if (lane == 0) red[w] = s;
    __syncthreads();
    if (tid == 0) { float t2 = 0.f; for (int q = 0; q < 8; ++q) t2 += red[q]; red[0] = t2; }
    __syncthreads();
    float mean = red[0] * (1.f / 512.f);
    float d0 = a0 - mean, d1 = a1 - mean;
    float v = d0 * d0 + d1 * d1;
    __syncthreads();
#pragma unroll
    for (int o = 16; o; o >>= 1) v += __shfl_xor_sync(0xFFFFFFFFu, v, o);
    if (lane == 0) red[w] = v;
    __syncthreads();
    if (tid == 0) { float t2 = 0.f; for (int q = 0; q < 8; ++q) t2 += red[q]; red[0] = t2; }
    __syncthreads();
    float var = red[0] * (1.f / 512.f);
    float inv = 1.f / sqrtf(var + 1e-12f);

    float* o = d_out_f + (size_t)z * 131072 + (size_t)row * 512;
    o[tid]       = d0 * inv * ln_w[tid]       + ln_b[tid];
    o[tid + 256] = d1 * inv * ln_w[tid + 256] + ln_b[tid + 256];
}

// =====================================================================
extern "C" void kernel_launch(void* const* d_in, const int* in_sizes, int n_in,
                              void* d_out, int out_size)
{
    const float* x_m    = (const float*)d_in[0];
    const float* x_c    = (const float*)d_in[1];
    const float* b_m    = (const float*)d_in[2];
    const float* b_c    = (const float*)d_in[3];
    const float* bb_m   = (const float*)d_in[4];
    const float* bb_c   = (const float*)d_in[5];
    const float* p_m    = (const float*)d_in[6];
    const float* p_c    = (const float*)d_in[7];
    const float* W_xm   = (const float*)d_in[8];
    const float* W_xc   = (const float*)d_in[9];
    const float* W_bm   = (const float*)d_in[10];
    const float* W_bc   = (const float*)d_in[11];
    const float* Wq1_w  = (const float*)d_in[12];
    const float* Wq1_b  = (const float*)d_in[13];
    const float* Wq2_w  = (const float*)d_in[14];
    const float* Wq2_b  = (const float*)d_in[15];
    const float* Wk1_w  = (const float*)d_in[16];
    const float* Wk1_b  = (const float*)d_in[17];
    const float* Wk2_w  = (const float*)d_in[18];
    const float* Wk2_b  = (const float*)d_in[19];
    const float* mean_w = (const float*)d_in[20];
    const float* mean_b = (const float*)d_in[21];
    const float* cov_w  = (const float*)d_in[22];
    const float* cov_b  = (const float*)d_in[23];
    const float* ln_w   = (const float*)d_in[24];
    const float* ln_b   = (const float*)d_in[25];
    const int*   b_seq  = (const int*)d_in[26];

    float* out = (float*)d_out;
    float* out_probs = out + 262144;   // [mean | cov | probs]

    cudaFuncSetAttribute(gemm_fused, cudaFuncAttributeMaxDynamicSharedMemorySize, PROJ_SMEM);

    prep_all<<<3586, 256>>>(x_m, b_m, x_c, b_c, W_xm, W_bm, W_xc, W_bc, b_seq);
    gemm_fused<<<168, 256, PROJ_SMEM>>>(p_m, bb_m,
                                        Wq1_w, Wq1_b, Wq2_w, Wq2_b,
                                        Wk1_w, Wk1_b, Wk2_w, Wk2_b);
    build_fqfk<<<1024, 128>>>(bb_c, p_c, b_seq);
    scores_kernel<<<dim3(16, 16, 8), 128>>>();
    softmax_ctx_kernel<<<128, 256>>>(out_probs);
    outgemm_kernel<<<dim3(8, 8, 2), 128>>>(mean_w, mean_b, cov_w, cov_b, x_m, x_c);
    ln_kernel<<<512, 256>>>(ln_w, ln_b, out);
}